// round 7
// baseline (speedup 1.0000x reference)
#include <cuda_runtime.h>
#include <cuda_bf16.h>

// Problem constants (fixed by the reference)
#define BATCH 16
#define MCTRL 64          // control points per axis
#define DEG   3           // degree (P == Q == 3)
#define LKNOT 68          // M + P + 1
#define OUTT  256         // OUT_U == OUT_V
#define UBLK  8           // u-rows per block

// ---------------------------------------------------------------------------
// Fused kernel: per-block basis recompute + separable tensor-product eval.
//
// Reference builds V from knot_u and v-linspace == u-linspace, so Nv == Nu
// and vspan == uspan: one basis table per batch serves both axes. Each block
// recomputes it locally (cheap) instead of a separate kernel + global round
// trip. Thread tid's basis IS the v-side weights for v = tid (kept in regs);
// the 8 u-side weights are read from shared.
// ---------------------------------------------------------------------------
__global__ void __launch_bounds__(OUTT) surf_kernel(
    const float* __restrict__ ctrl,
    const float* __restrict__ knot_u,
    float* __restrict__ out) {
    const int b   = blockIdx.y;
    const int u0  = blockIdx.x * UBLK;
    const int tid = threadIdx.x;

    __shared__ float  K[LKNOT];
    __shared__ float  U[LKNOT];
    __shared__ float4 sN[OUTT];                 // basis per t
    __shared__ int    sS[OUTT];                 // span  per t
    __shared__ float  ts[UBLK][3][MCTRL + 4];   // u-contracted rows (xyz)

    // ---- knots -> normalized U ----------------------------------------
    if (tid < LKNOT) K[tid] = knot_u[b * LKNOT + tid];
    __syncthreads();

    if (tid < LKNOT) {
        // one pass: own prefix + total (branch-free capture)
        float c = 0.0f, pre = 0.0f;
        #pragma unroll 1
        for (int j = 0; j < LKNOT; j++) {
            c += K[j];
            if (j == tid) pre = c;
        }
        U[tid] = (pre - K[0]) / (c - K[0]);     // (cs[i]-cs[0])/(cs[-1]-cs[0])
    }
    __syncthreads();

    // ---- per-thread t: span + Cox-de Boor basis ------------------------
    const float step = (1.0f - 2e-5f) / (float)(OUTT - 1);
    const float t    = 1e-5f + (float)tid * step;

    // find_span: first argmin over s in [DEG, LKNOT-DEG-1] of (d>1e-8 ? d : 1)
    float best = 1e30f;
    int   span = DEG;
    #pragma unroll 1
    for (int s = DEG; s <= LKNOT - DEG - 1; s++) {   // s = 3..64
        float d    = t - U[s];
        float cand = (d > 1e-8f) ? d : 1.0f;
        if (cand < best) { best = cand; span = s; }
    }

    float Ni[DEG + 1];
    Ni[0] = 1.0f;
    #pragma unroll
    for (int k = 1; k <= DEG; k++) {
        float saved = 0.0f;
        #pragma unroll
        for (int r = 0; r < k; r++) {
            float K1   = U[span + r + 1];
            float K2   = U[span + 1 - k + r];
            float temp = Ni[r] / ((K1 - t) + (t - K2));
            Ni[r]      = saved + (K1 - t) * temp;
            saved      = (t - K2) * temp;
        }
        Ni[k] = saved;
    }

    sN[tid] = make_float4(Ni[0], Ni[1], Ni[2], Ni[3]);
    sS[tid] = span;
    __syncthreads();

    // ---- staging: u-contraction, 8*64 = 512 (uu, col) pairs ------------
    #pragma unroll
    for (int p = 0; p < (UBLK * MCTRL) / OUTT; p++) {
        const int idx = tid + p * OUTT;
        const int uu  = idx >> 6;           // 0..7
        const int j   = idx & 63;           // 0..63
        const float4 nu = sN[u0 + uu];
        const int    su = sS[u0 + uu] - DEG;           // 0..60
        const float4* cp = (const float4*)ctrl
                         + (size_t)b * MCTRL * MCTRL + (size_t)su * MCTRL + j;
        const float4 c0 = cp[0 * MCTRL];
        const float4 c1 = cp[1 * MCTRL];
        const float4 c2 = cp[2 * MCTRL];
        const float4 c3 = cp[3 * MCTRL];
        float x = nu.x * c0.x, y = nu.x * c0.y, z = nu.x * c0.z;
        x = fmaf(nu.y, c1.x, x); y = fmaf(nu.y, c1.y, y); z = fmaf(nu.y, c1.z, z);
        x = fmaf(nu.z, c2.x, x); y = fmaf(nu.z, c2.y, y); z = fmaf(nu.z, c2.z, z);
        x = fmaf(nu.w, c3.x, x); y = fmaf(nu.w, c3.y, y); z = fmaf(nu.w, c3.z, z);
        ts[uu][0][j] = x; ts[uu][1][j] = y; ts[uu][2][j] = z;
    }
    if (tid < UBLK * 4) {                   // pad (sv <= 60 analytically)
        const int uu = tid >> 2, j = tid & 3;
        ts[uu][0][MCTRL + j] = 0.0f;
        ts[uu][1][MCTRL + j] = 0.0f;
        ts[uu][2][MCTRL + j] = 0.0f;
    }
    __syncthreads();

    // ---- v-contraction: weights already in registers -------------------
    const int sv = span - DEG;              // 0..60
    float* obase = out + ((size_t)(b * OUTT + u0) * OUTT + tid) * 3;
    #pragma unroll
    for (int uu = 0; uu < UBLK; uu++) {
        const float* px = ts[uu][0];
        const float* py = ts[uu][1];
        const float* pz = ts[uu][2];
        float ax = Ni[0] * px[sv];
        float ay = Ni[0] * py[sv];
        float az = Ni[0] * pz[sv];
        ax = fmaf(Ni[1], px[sv + 1], ax); ay = fmaf(Ni[1], py[sv + 1], ay); az = fmaf(Ni[1], pz[sv + 1], az);
        ax = fmaf(Ni[2], px[sv + 2], ax); ay = fmaf(Ni[2], py[sv + 2], ay); az = fmaf(Ni[2], pz[sv + 2], az);
        ax = fmaf(Ni[3], px[sv + 3], ax); ay = fmaf(Ni[3], py[sv + 3], ay); az = fmaf(Ni[3], pz[sv + 3], az);
        float* o = obase + (size_t)uu * OUTT * 3;
        o[0] = ax; o[1] = ay; o[2] = az;
    }
}

// ---------------------------------------------------------------------------
extern "C" void kernel_launch(void* const* d_in, const int* in_sizes, int n_in,
                              void* d_out, int out_size) {
    const float* ctrl   = (const float*)d_in[0];   // [16,64,64,4]
    const float* knot_u = (const float*)d_in[1];   // [16,68]
    (void)in_sizes; (void)n_in; (void)out_size;

    float* out = (float*)d_out;                    // [16,256,256,3]

    dim3 grid(OUTT / UBLK, BATCH);
    surf_kernel<<<grid, OUTT>>>(ctrl, knot_u, out);
}

// round 8
// speedup vs baseline: 1.3652x; 1.3652x over previous
#include <cuda_runtime.h>
#include <cuda_bf16.h>

// Problem constants (fixed by the reference)
#define BATCH 16
#define MCTRL 64          // control points per axis
#define DEG   3           // degree (P == Q == 3)
#define LKNOT 68          // M + P + 1
#define OUTT  256         // OUT_U == OUT_V
#define UBLK  16          // u-rows per block

// ---------------------------------------------------------------------------
// Fused kernel: fast per-block basis recompute + separable tensor-product eval.
//
// Reference builds V from knot_u and v-linspace == u-linspace, so Nv == Nu
// and vspan == uspan: one basis table per batch serves both axes. Thread
// tid's basis IS the v-side weights for v = tid (kept in regs); the 16
// u-side weights are read from shared.
// ---------------------------------------------------------------------------
__global__ void __launch_bounds__(OUTT) surf_kernel(
    const float* __restrict__ ctrl,
    const float* __restrict__ knot_u,
    float* __restrict__ out) {
    const int b   = blockIdx.y;
    const int u0  = blockIdx.x * UBLK;
    const int tid = threadIdx.x;

    __shared__ float  U[LKNOT];
    __shared__ float4 sN[OUTT];                 // basis per t
    __shared__ int    sS[OUTT];                 // span  per t
    __shared__ float  ts[UBLK][3][MCTRL + 4];   // u-contracted rows (xyz)

    // ---- warp 0: load knots, shuffle-scan cumsum, normalize, store U ----
    if (tid < 32) {
        float vv[3];
        float carry = 0.0f;
        #pragma unroll
        for (int c = 0; c < 3; c++) {
            const int i = c * 32 + tid;
            float x = (i < LKNOT) ? knot_u[b * LKNOT + i] : 0.0f;
            #pragma unroll
            for (int d = 1; d < 32; d <<= 1) {
                float n = __shfl_up_sync(0xffffffffu, x, d);
                if (tid >= d) x += n;
            }
            x += carry;
            vv[c] = x;
            carry = __shfl_sync(0xffffffffu, x, 31);   // cs at chunk end
        }
        // carry == cs[LKNOT-1] (padded zeros beyond 67 don't change it)
        const float c0  = __shfl_sync(0xffffffffu, vv[0], 0);   // cs[0]
        const float inv = 1.0f / (carry - c0);
        #pragma unroll
        for (int c = 0; c < 3; c++) {
            const int i = c * 32 + tid;
            if (i < LKNOT) U[i] = (vv[c] - c0) * inv;
        }
    }
    __syncthreads();

    // ---- per-thread t: branchless span + Cox-de Boor basis -------------
    const float step = (1.0f - 2e-5f) / (float)(OUTT - 1);
    const float t    = 1e-5f + (float)tid * step;

    // Validity (t-U[s] > 1e-8) is a prefix in s (U increasing) and valid
    // candidates are strictly decreasing, so reference argmin == last valid:
    //   span = DEG + cnt - 1   (cnt >= 1 always; clamp for safety)
    int cnt = 0;
    #pragma unroll
    for (int s = DEG; s <= LKNOT - DEG - 1; s++)   // s = 3..64, independent
        cnt += ((t - U[s]) > 1e-8f) ? 1 : 0;
    const int span = DEG + ((cnt > 0) ? (cnt - 1) : 0);

    float Ni[DEG + 1];
    Ni[0] = 1.0f;
    #pragma unroll
    for (int k = 1; k <= DEG; k++) {
        float saved = 0.0f;
        #pragma unroll
        for (int r = 0; r < k; r++) {
            float K1   = U[span + r + 1];
            float K2   = U[span + 1 - k + r];
            float temp = Ni[r] / ((K1 - t) + (t - K2));
            Ni[r]      = saved + (K1 - t) * temp;
            saved      = (t - K2) * temp;
        }
        Ni[k] = saved;
    }

    sN[tid] = make_float4(Ni[0], Ni[1], Ni[2], Ni[3]);
    sS[tid] = span;
    __syncthreads();

    // ---- staging: u-contraction, 16*64 = 1024 (uu, col) pairs ----------
    #pragma unroll
    for (int p = 0; p < (UBLK * MCTRL) / OUTT; p++) {
        const int idx = tid + p * OUTT;
        const int uu  = idx >> 6;           // 0..15
        const int j   = idx & 63;           // 0..63
        const float4 nu = sN[u0 + uu];
        const int    su = sS[u0 + uu] - DEG;           // 0..60
        const float4* cp = (const float4*)ctrl
                         + (size_t)b * MCTRL * MCTRL + (size_t)su * MCTRL + j;
        const float4 c0 = cp[0 * MCTRL];
        const float4 c1 = cp[1 * MCTRL];
        const float4 c2 = cp[2 * MCTRL];
        const float4 c3 = cp[3 * MCTRL];
        float x = nu.x * c0.x, y = nu.x * c0.y, z = nu.x * c0.z;
        x = fmaf(nu.y, c1.x, x); y = fmaf(nu.y, c1.y, y); z = fmaf(nu.y, c1.z, z);
        x = fmaf(nu.z, c2.x, x); y = fmaf(nu.z, c2.y, y); z = fmaf(nu.z, c2.z, z);
        x = fmaf(nu.w, c3.x, x); y = fmaf(nu.w, c3.y, y); z = fmaf(nu.w, c3.z, z);
        ts[uu][0][j] = x; ts[uu][1][j] = y; ts[uu][2][j] = z;
    }
    if (tid < UBLK * 4) {                   // pad (sv <= 60 analytically)
        const int uu = tid >> 2, j = tid & 3;
        ts[uu][0][MCTRL + j] = 0.0f;
        ts[uu][1][MCTRL + j] = 0.0f;
        ts[uu][2][MCTRL + j] = 0.0f;
    }
    __syncthreads();

    // ---- v-contraction: weights already in registers -------------------
    const int sv = span - DEG;              // 0..60
    float* obase = out + ((size_t)(b * OUTT + u0) * OUTT + tid) * 3;
    #pragma unroll
    for (int uu = 0; uu < UBLK; uu++) {
        const float* px = ts[uu][0];
        const float* py = ts[uu][1];
        const float* pz = ts[uu][2];
        float ax = Ni[0] * px[sv];
        float ay = Ni[0] * py[sv];
        float az = Ni[0] * pz[sv];
        ax = fmaf(Ni[1], px[sv + 1], ax); ay = fmaf(Ni[1], py[sv + 1], ay); az = fmaf(Ni[1], pz[sv + 1], az);
        ax = fmaf(Ni[2], px[sv + 2], ax); ay = fmaf(Ni[2], py[sv + 2], ay); az = fmaf(Ni[2], pz[sv + 2], az);
        ax = fmaf(Ni[3], px[sv + 3], ax); ay = fmaf(Ni[3], py[sv + 3], ay); az = fmaf(Ni[3], pz[sv + 3], az);
        float* o = obase + (size_t)uu * OUTT * 3;
        o[0] = ax; o[1] = ay; o[2] = az;
    }
}

// ---------------------------------------------------------------------------
extern "C" void kernel_launch(void* const* d_in, const int* in_sizes, int n_in,
                              void* d_out, int out_size) {
    const float* ctrl   = (const float*)d_in[0];   // [16,64,64,4]
    const float* knot_u = (const float*)d_in[1];   // [16,68]
    (void)in_sizes; (void)n_in; (void)out_size;

    float* out = (float*)d_out;                    // [16,256,256,3]

    dim3 grid(OUTT / UBLK, BATCH);
    surf_kernel<<<grid, OUTT>>>(ctrl, knot_u, out);
}